// round 2
// baseline (speedup 1.0000x reference)
#include <cuda_runtime.h>

#define NEXP 5
#define HID  20

typedef unsigned long long ull;

__device__ __forceinline__ ull pack2(float lo, float hi) {
    ull r;
    asm("mov.b64 %0, {%1, %2};" : "=l"(r) : "f"(lo), "f"(hi));
    return r;
}
__device__ __forceinline__ void unpack2(ull v, float& lo, float& hi) {
    asm("mov.b64 {%0, %1}, %2;" : "=f"(lo), "=f"(hi) : "l"(v));
}
__device__ __forceinline__ ull fma2(ull a, ull b, ull c) {
    ull r;
    asm("fma.rn.f32x2 %0, %1, %2, %3;" : "=l"(r) : "l"(a), "l"(b), "l"(c));
    return r;
}
__device__ __forceinline__ ull relu2(ull v) {
    float lo, hi;
    unpack2(v, lo, hi);
    return pack2(fmaxf(lo, 0.0f), fmaxf(hi, 0.0f));
}

__global__ __launch_bounds__(256) void moe_kernel(
    const float* __restrict__ x,
    const float* __restrict__ W1, const float* __restrict__ b1,
    const float* __restrict__ W2, const float* __restrict__ b2,
    const float* __restrict__ Wg, const float* __restrict__ bg,
    float* __restrict__ out_mixed, float* __restrict__ out_gate,
    int ngroups)
{
    // Duplicate-packed weights: each ull holds {w, w} so it is directly an
    // f32x2 broadcast operand. Per (e,h): 4 x LDS.128 feeds 12 FFMA2.
    __shared__ ulonglong2 s_w1a[NEXP * HID];  // {w1x2, w1y2}
    __shared__ ulonglong2 s_w1b[NEXP * HID];  // {w1z2, b1_2}
    __shared__ ulonglong2 s_w2a[NEXP * HID];  // {w2x2, w2y2}
    __shared__ ull        s_w2z[NEXP * HID];  // w2z2
    __shared__ ull        s_b2d[NEXP][3];     // duplicated b2
    __shared__ float4     s_gw[NEXP];         // {Wgx, Wgy, Wgz, bg}

    int t = threadIdx.x;
    if (t < NEXP * HID) {
        int e = t / HID, h = t % HID;
        float w1x = W1[(e * 3 + 0) * HID + h];
        float w1y = W1[(e * 3 + 1) * HID + h];
        float w1z = W1[(e * 3 + 2) * HID + h];
        float bb1 = b1[e * HID + h];
        s_w1a[t] = make_ulonglong2(pack2(w1x, w1x), pack2(w1y, w1y));
        s_w1b[t] = make_ulonglong2(pack2(w1z, w1z), pack2(bb1, bb1));
        float w2x = W2[(e * HID + h) * 3 + 0];
        float w2y = W2[(e * HID + h) * 3 + 1];
        float w2z = W2[(e * HID + h) * 3 + 2];
        s_w2a[t] = make_ulonglong2(pack2(w2x, w2x), pack2(w2y, w2y));
        s_w2z[t] = pack2(w2z, w2z);
    } else if (t < NEXP * HID + NEXP) {
        int e = t - NEXP * HID;
        s_gw[e] = make_float4(Wg[0 * NEXP + e], Wg[1 * NEXP + e], Wg[2 * NEXP + e], bg[e]);
        s_b2d[e][0] = pack2(b2[e * 3 + 0], b2[e * 3 + 0]);
        s_b2d[e][1] = pack2(b2[e * 3 + 1], b2[e * 3 + 1]);
        s_b2d[e][2] = pack2(b2[e * 3 + 2], b2[e * 3 + 2]);
    }
    __syncthreads();

    int gid = blockIdx.x * blockDim.x + threadIdx.x;  // group of 4 tokens
    if (gid >= ngroups) return;

    // Load 4 tokens' x (12 floats), repack into 2 token-pairs of f32x2.
    const float4* x4 = (const float4*)x;
    float4 xa = x4[3 * gid + 0];
    float4 xb = x4[3 * gid + 1];
    float4 xc = x4[3 * gid + 2];
    // token k components: x0 = {xa.x, xa.w, xb.z, xc.y}, x1 = {xa.y, xb.x, xb.w, xc.z}, x2 = {xa.z, xb.y, xc.x, xc.w}
    ull x0p[2] = { pack2(xa.x, xa.w), pack2(xb.z, xc.y) };
    ull x1p[2] = { pack2(xa.y, xb.x), pack2(xb.w, xc.z) };
    ull x2p[2] = { pack2(xa.z, xb.y), pack2(xc.x, xc.w) };

    // ---- Gate (scalar; small) ----
    float x0s[4] = {xa.x, xa.w, xb.z, xc.y};
    float x1s[4] = {xa.y, xb.x, xb.w, xc.z};
    float x2s[4] = {xa.z, xb.y, xc.x, xc.w};
    float g[4][NEXP];
    #pragma unroll
    for (int e = 0; e < NEXP; e++) {
        float4 w = s_gw[e];
        #pragma unroll
        for (int k = 0; k < 4; k++)
            g[k][e] = fmaf(x0s[k], w.x, fmaf(x1s[k], w.y, fmaf(x2s[k], w.z, w.w)));
    }
    #pragma unroll
    for (int k = 0; k < 4; k++) {
        float m = g[k][0];
        #pragma unroll
        for (int e = 1; e < NEXP; e++) m = fmaxf(m, g[k][e]);
        float s = 0.0f;
        #pragma unroll
        for (int e = 0; e < NEXP; e++) { g[k][e] = __expf(g[k][e] - m); s += g[k][e]; }
        float inv = __fdividef(1.0f, s);
        #pragma unroll
        for (int e = 0; e < NEXP; e++) g[k][e] *= inv;
    }

    // Store gate outputs now (frees scalar g live ranges early).
    float4* og = (float4*)out_gate;
    og[5 * gid + 0] = make_float4(g[0][0], g[0][1], g[0][2], g[0][3]);
    og[5 * gid + 1] = make_float4(g[0][4], g[1][0], g[1][1], g[1][2]);
    og[5 * gid + 2] = make_float4(g[1][3], g[1][4], g[2][0], g[2][1]);
    og[5 * gid + 3] = make_float4(g[2][2], g[2][3], g[2][4], g[3][0]);
    og[5 * gid + 4] = make_float4(g[3][1], g[3][2], g[3][3], g[3][4]);

    // Packed gate per token-pair for the mixing FMA2s.
    ull gp[2][NEXP];
    #pragma unroll
    for (int e = 0; e < NEXP; e++) {
        gp[0][e] = pack2(g[0][e], g[1][e]);
        gp[1][e] = pack2(g[2][e], g[3][e]);
    }

    // ---- Experts: packed fc1 + ReLU + fc2 (bias folded into acc init) ----
    ull zero = pack2(0.0f, 0.0f);
    ull mix0[2] = {zero, zero}, mix1[2] = {zero, zero}, mix2[2] = {zero, zero};

    for (int e = 0; e < NEXP; e++) {
        ull acc0[2], acc1[2], acc2[2];
        ull bb0 = s_b2d[e][0], bb1v = s_b2d[e][1], bb2 = s_b2d[e][2];
        acc0[0] = bb0; acc0[1] = bb0;
        acc1[0] = bb1v; acc1[1] = bb1v;
        acc2[0] = bb2; acc2[1] = bb2;
        #pragma unroll
        for (int h = 0; h < HID; h++) {
            int idx = e * HID + h;
            ulonglong2 w1a = s_w1a[idx];
            ulonglong2 w1b = s_w1b[idx];
            ulonglong2 w2a = s_w2a[idx];
            ull        w2z = s_w2z[idx];
            #pragma unroll
            for (int p = 0; p < 2; p++) {
                ull hv = fma2(x0p[p], w1a.x, fma2(x1p[p], w1a.y, fma2(x2p[p], w1b.x, w1b.y)));
                hv = relu2(hv);
                acc0[p] = fma2(hv, w2a.x, acc0[p]);
                acc1[p] = fma2(hv, w2a.y, acc1[p]);
                acc2[p] = fma2(hv, w2z,  acc2[p]);
            }
        }
        #pragma unroll
        for (int p = 0; p < 2; p++) {
            mix0[p] = fma2(gp[p][e], acc0[p], mix0[p]);
            mix1[p] = fma2(gp[p][e], acc1[p], mix1[p]);
            mix2[p] = fma2(gp[p][e], acc2[p], mix2[p]);
        }
    }

    // ---- Unpack mixed and store (12 floats, 3x STG.128) ----
    float m0[4], m1[4], m2[4];
    unpack2(mix0[0], m0[0], m0[1]); unpack2(mix0[1], m0[2], m0[3]);
    unpack2(mix1[0], m1[0], m1[1]); unpack2(mix1[1], m1[2], m1[3]);
    unpack2(mix2[0], m2[0], m2[1]); unpack2(mix2[1], m2[2], m2[3]);

    float4* om = (float4*)out_mixed;
    om[3 * gid + 0] = make_float4(m0[0], m1[0], m2[0], m0[1]);
    om[3 * gid + 1] = make_float4(m1[1], m2[1], m0[2], m1[2]);
    om[3 * gid + 2] = make_float4(m2[2], m0[3], m1[3], m2[3]);
}

extern "C" void kernel_launch(void* const* d_in, const int* in_sizes, int n_in,
                              void* d_out, int out_size)
{
    // Input order per setup_inputs: x, W1, b1, W2, b2, Wg, bg
    const float* x  = (const float*)d_in[0];
    const float* W1 = (const float*)d_in[1];
    const float* b1 = (const float*)d_in[2];
    const float* W2 = (const float*)d_in[3];
    const float* b2 = (const float*)d_in[4];
    const float* Wg = (const float*)d_in[5];
    const float* bg = (const float*)d_in[6];

    int B = in_sizes[0] / 3;           // x is [B, 3]
    int ngroups = B / 4;               // 4 tokens per thread

    float* out_mixed = (float*)d_out;            // [B, 3]
    float* out_gate  = (float*)d_out + 3 * B;    // [B, 5]

    int threads = 256;
    int blocks = (ngroups + threads - 1) / threads;
    moe_kernel<<<blocks, threads>>>(x, W1, b1, W2, b2, Wg, bg,
                                    out_mixed, out_gate, ngroups);
}